// round 14
// baseline (speedup 1.0000x reference)
#include <cuda_runtime.h>
#include <cuda_bf16.h>

#define NBX 512
#define NBY 512
#define KK  5
#define TARGET_AREA 0.9f
#define MS  520                     // padded map row stride (floats)
#define MAPSZ (512 * MS + 16)       // max used idx 511*520+515

#define GRID_P 148                  // persistent: 1 block/SM, one wave
#define TPB_P  1024
#define NTILES 256                  // 16x16 tiles of 32x32 cells

// ---- static device scratch (no runtime allocation allowed) ----
// M copies: logical (x,y) stored at idx x*MS + (y - k) + 4   (copy k)
// T copies: logical (x,y) stored at idx y*MS + (x - k) + 4   (copy k, transposed)
__device__ __align__(16) float g_M[4][MAPSZ];
__device__ __align__(16) float g_T[4][MAPSZ];
__device__ float g_sum;             // reset by last ticket
__device__ int   g_done;
__device__ int   g_bar;             // grid barrier; reset by last ticket

__device__ __forceinline__ void red_add_v4(float* a, float v0, float v1, float v2, float v3) {
    asm volatile("red.global.add.v4.f32 [%0], {%1, %2, %3, %4};"
                 :: "l"(a), "f"(v0), "f"(v1), "f"(v2), "f"(v3) : "memory");
}
__device__ __forceinline__ void red_add_f(float* a, float v) {
    asm volatile("red.global.add.f32 [%0], %1;" :: "l"(a), "f"(v) : "memory");
}

// 5 bell-potential values over window starting at s0 (zeros only at the ends)
__device__ __forceinline__ void pot5(float coord, float s, int s0, float* p) {
    float ctr = coord + 0.5f * s;
    float a   = 4.0f / ((s + 2.0f) * (s + 4.0f));
    float cb  = s * (2.0f / (s + 4.0f));
    float p1  = 0.5f * s + 1.0f;
    float p2  = 0.5f * s + 2.0f;
    float d0  = ctr - ((float)s0 + 0.5f);
#pragma unroll
    for (int k = 0; k < KK; k++) {
        float d = fabsf(d0 - (float)k);
        float v;
        if (d < p1)      v = s * (1.0f - a * d * d);
        else if (d < p2) { float t = d - p2; v = cb * t * t; }
        else             v = 0.0f;
        p[k] = v;
    }
}

// strip leading zeros from q[0..4] (shifting zeros in at the top); returns shift
__device__ __forceinline__ int strip5(float* q) {
    int sft = 0;
#pragma unroll
    for (int t = 0; t < 4; t++) {
        if (q[0] == 0.0f) {
            q[0] = q[1]; q[1] = q[2]; q[2] = q[3]; q[3] = q[4]; q[4] = 0.0f;
            sft++;
        }
    }
    return sft;
}

// Per-node deposit: <=5 row-v4 REDs + (P=.5) column T-v4 + (P~.125) corner
// (at the REDG request floor: 5.125 req/node vs 5.06 covering bound)
__device__ __forceinline__ void deposit_node(float x, float y, float sx, float sy) {
    int sx0 = min(max((int)floorf(x - 2.0f), 0), NBX - KK);
    int sy0 = min(max((int)floorf(y - 2.0f), 0), NBY - KK);

    float px[KK], py[KK];
    pot5(x, sx, sx0, px);
    pot5(y, sy, sy0, py);

    float q[KK] = {py[0], py[1], py[2], py[3], py[4]};
    int ys = sy0 + strip5(q);
    float colv = q[4];                 // nonzero only when shift==0 && width==5
    float* Mk = g_M[ys & 3];
    int ycol = (ys & ~3) + 4;

#pragma unroll
    for (int r = 0; r < KK; r++) {
        float vx = px[r];
        if (vx != 0.0f)
            red_add_v4(Mk + (sx0 + r) * MS + ycol,
                       vx * q[0], vx * q[1], vx * q[2], vx * q[3]);
    }

    if (colv != 0.0f) {                // 5th column at logical y = sy0+4
        float c[KK] = {px[0], px[1], px[2], px[3], px[4]};
        int xs = sx0 + strip5(c);
        float corner = c[4];
        float* Tk = g_T[xs & 3];
        red_add_v4(Tk + (sy0 + 4) * MS + (xs & ~3) + 4,
                   colv * c[0], colv * c[1], colv * c[2], colv * c[3]);
        if (corner != 0.0f)
            red_add_f(&g_M[0][(sx0 + 4) * MS + (sy0 + 4) + 4], corner * colv);
    }
}

// ---------------------------------------------------------------------------
// ONE persistent kernel: scatter -> grid barrier -> finish (warm SMs, no
// second launch ramp). 148 blocks x 1024 threads, 1 block/SM resident.
// ---------------------------------------------------------------------------
__global__ void __launch_bounds__(TPB_P, 1) fused_kernel(
    const float* __restrict__ pos,
    const float* __restrict__ sxs,
    const float* __restrict__ sys,
    const float* __restrict__ initial,
    float* __restrict__ out,
    int n)
{
    __shared__ float ts[32][33];       // transpose buffer, conflict-free
    __shared__ float sd[32];

    const int tid  = threadIdx.x;
    const int lane = tid & 31;
    const int row  = tid >> 5;         // 0..31

    // ===== Phase A: scatter (grid-stride) =====
    for (int i = blockIdx.x * TPB_P + tid; i < n; i += GRID_P * TPB_P) {
        float x = pos[i];
        deposit_node(x, pos[n + i], sxs[i], sys[i]);
    }

    // ===== Phase B: grid barrier (all 148 blocks resident => no deadlock) =====
    __threadfence();
    __syncthreads();
    if (tid == 0) {
        atomicAdd(&g_bar, 1);
        while (atomicAdd(&g_bar, 0) < GRID_P) { __nanosleep(64); }
    }
    __syncthreads();

    // ===== Phase C: finish — grid-stride over 256 tiles (<=2 per block) =====
    float acc = 0.0f;
    for (int t = blockIdx.x; t < NTILES; t += GRID_P) {
        int X0 = (t & 15) << 5;
        int Y0 = (t >> 4) << 5;

        int tBase = (Y0 + row) * MS + X0 + lane;   // T: coalesced along x
        int xgM   = X0 + row;
        int mBase = xgM * MS + (Y0 + lane);        // M: coalesced along y
        int iIdx  = xgM * NBY + (Y0 + lane);

        // all 9 independent loads back-to-back (one latency window)
        float t0 = g_T[0][tBase + 4];
        float t1 = g_T[1][tBase + 3];
        float t2 = g_T[2][tBase + 2];
        float t3 = g_T[3][tBase + 1];
        float m0 = g_M[0][mBase + 4];
        float m1 = g_M[1][mBase + 3];
        float m2 = g_M[2][mBase + 2];
        float m3 = g_M[3][mBase + 1];
        float i0 = initial[iIdx];

        ts[row][lane] = t0 + t1 + t2 + t3;
        __syncthreads();

        float v = i0 + m0 + m1 + m2 + m3 + ts[lane][row];
        float d = v - TARGET_AREA;
        acc += d * d;

        // zero own region (streaming stores, decoupled from loads)
#pragma unroll
        for (int k = 0; k < 4; k++)
            g_T[k][tBase + 4 - k] = 0.0f;
#pragma unroll
        for (int k = 0; k < 4; k++)
            g_M[k][mBase + 4 - k] = 0.0f;
        __syncthreads();               // ts reuse safety for next tile
    }

    // ===== block reduce + ticketed out-write / full state reset =====
#pragma unroll
    for (int off = 16; off > 0; off >>= 1)
        acc += __shfl_xor_sync(0xFFFFFFFF, acc, off);
    if (lane == 0) sd[row] = acc;
    __syncthreads();
    if (tid < 32) {
        float v2 = sd[tid];
#pragma unroll
        for (int off = 16; off > 0; off >>= 1)
            v2 += __shfl_xor_sync(0xFFFFFFFF, v2, off);
        if (tid == 0) {
            atomicAdd(&g_sum, v2);
            __threadfence();
            int tk = atomicAdd(&g_done, 1);
            if (tk == GRID_P - 1) {    // every block already passed the barrier
                out[0] = g_sum;
                g_sum  = 0.0f;         // restore invariants for next replay
                g_done = 0;
                g_bar  = 0;
            }
        }
    }
}

// ---------------------------------------------------------------------------
extern "C" void kernel_launch(void* const* d_in, const int* in_sizes, int n_in,
                              void* d_out, int out_size) {
    const float* pos = (const float*)d_in[0];
    const float* sx  = (const float*)d_in[1];
    const float* sy  = (const float*)d_in[2];
    // d_in[3..8]: ax..cy — recomputed analytically; d_in[9..10]: bin centers — analytic
    const float* initial = (const float*)d_in[11];
    float* out = (float*)d_out;

    int n = in_sizes[1];

    fused_kernel<<<GRID_P, TPB_P>>>(pos, sx, sy, initial, out, n);
}

// round 15
// speedup vs baseline: 1.2042x; 1.2042x over previous
#include <cuda_runtime.h>
#include <cuda_bf16.h>

#define NBX 512
#define NBY 512
#define KK  5
#define TARGET_AREA 0.9f
#define MS  520                     // padded map row stride (floats)
#define MAPSZ (512 * MS + 16)       // max used idx 511*520+515

#define FIN_BLOCKS 128              // one balanced wave; 2 tiles (32x32) per block

// ---- static device scratch (no runtime allocation allowed) ----
// M copies: logical (x,y) stored at idx x*MS + (y - k) + 4   (copy k)
// T copies: logical (x,y) stored at idx y*MS + (x - k) + 4   (copy k, transposed)
__device__ __align__(16) float g_M[4][MAPSZ];
__device__ __align__(16) float g_T[4][MAPSZ];
__device__ float g_sum;             // reset by finish's last block
__device__ int   g_done;

__device__ __forceinline__ void red_add_v4(float* a, float v0, float v1, float v2, float v3) {
    asm volatile("red.global.add.v4.f32 [%0], {%1, %2, %3, %4};"
                 :: "l"(a), "f"(v0), "f"(v1), "f"(v2), "f"(v3) : "memory");
}
__device__ __forceinline__ void red_add_f(float* a, float v) {
    asm volatile("red.global.add.f32 [%0], %1;" :: "l"(a), "f"(v) : "memory");
}

// single bell value at integer-offset k from window start s0
__device__ __forceinline__ float bell1(float d0, float k, float s, float a,
                                       float cb, float p1, float p2) {
    float d = fabsf(d0 - k);
    float v;
    if (d < p1)      v = s * (1.0f - a * d * d);
    else if (d < p2) { float t = d - p2; v = cb * t * t; }
    else             v = 0.0f;
    return v;
}

// 5 bell-potential values over window starting at s0 (zeros only at the ends)
__device__ __forceinline__ void pot5(float coord, float s, int s0, float* p) {
    float ctr = coord + 0.5f * s;
    float a   = 4.0f / ((s + 2.0f) * (s + 4.0f));
    float cb  = s * (2.0f / (s + 4.0f));
    float p1  = 0.5f * s + 1.0f;
    float p2  = 0.5f * s + 2.0f;
    float d0  = ctr - ((float)s0 + 0.5f);
#pragma unroll
    for (int k = 0; k < KK; k++)
        p[k] = bell1(d0, (float)k, s, a, cb, p1, p2);
}

// strip leading zeros from q[0..4] (shifting zeros in at the top); returns shift
__device__ __forceinline__ int strip5(float* q) {
    int sft = 0;
#pragma unroll
    for (int t = 0; t < 4; t++) {
        if (q[0] == 0.0f) {
            q[0] = q[1]; q[1] = q[2]; q[2] = q[3]; q[3] = q[4]; q[4] = 0.0f;
            sft++;
        }
    }
    return sft;
}

// ---------------------------------------------------------------------------
// Scatter: register-lean (x potentials computed on the fly), 8 blocks/SM
// => 64 warps/SM resident. Per node: <=5 row-v4 REDs + (P=.5) column T-v4
// + (P~.125) corner scalar. Request count unchanged (5.125/node).
// ---------------------------------------------------------------------------
__global__ void __launch_bounds__(256, 8) scatter_kernel(
    const float* __restrict__ pos,
    const float* __restrict__ sxs,
    const float* __restrict__ sys,
    int n)
{
    int i = blockIdx.x * blockDim.x + threadIdx.x;
    if (i >= n) return;

    float x  = pos[i];
    float y  = pos[n + i];
    float sx = sxs[i];
    float sy = sys[i];

    int sx0 = min(max((int)floorf(x - 2.0f), 0), NBX - KK);
    int sy0 = min(max((int)floorf(y - 2.0f), 0), NBY - KK);

    // ---- y window: full array, strip, v4 lanes + leftover column ----
    float q[KK];
    pot5(y, sy, sy0, q);
    int ys = sy0 + strip5(q);
    float colv = q[4];                 // nonzero only when shift==0 && width==5
    float* Mk = g_M[ys & 3];
    int ycol = (ys & ~3) + 4;

    // ---- x params (per-row value computed on the fly; no px array) ----
    float ax  = 4.0f / ((sx + 2.0f) * (sx + 4.0f));
    float cbx = sx * (2.0f / (sx + 4.0f));
    float p1x = 0.5f * sx + 1.0f;
    float p2x = 0.5f * sx + 2.0f;
    float d0x = (x + 0.5f * sx) - ((float)sx0 + 0.5f);

#pragma unroll
    for (int r = 0; r < KK; r++) {
        float vx = bell1(d0x, (float)r, sx, ax, cbx, p1x, p2x);
        if (vx != 0.0f)
            red_add_v4(Mk + (sx0 + r) * MS + ycol,
                       vx * q[0], vx * q[1], vx * q[2], vx * q[3]);
    }

    if (colv != 0.0f) {                // 5th column at logical y = sy0+4
        float c[KK];
#pragma unroll
        for (int r = 0; r < KK; r++)
            c[r] = bell1(d0x, (float)r, sx, ax, cbx, p1x, p2x);
        int xs = sx0 + strip5(c);
        float corner = c[4];           // nonzero only when shift==0 && width==5
        float* Tk = g_T[xs & 3];
        red_add_v4(Tk + (sy0 + 4) * MS + (xs & ~3) + 4,
                   colv * c[0], colv * c[1], colv * c[2], colv * c[3]);
        if (corner != 0.0f)            // corner (sx0+4, sy0+4)
            red_add_f(&g_M[0][(sx0 + 4) * MS + (sy0 + 4) + 4], corner * colv);
    }
}

// ---------------------------------------------------------------------------
// Finish (R13 exact): 128 blocks x 1024 threads, TWO 32x32 tiles per block,
// all 18 global loads back-to-back, 32-wide coalesced, own-region zeroing,
// PDL prologue overlap.
// ---------------------------------------------------------------------------
__global__ void __launch_bounds__(1024) finish_kernel(
    const float* __restrict__ initial,
    float* __restrict__ out)
{
    __shared__ float ts[2][32][33];
    __shared__ float sd[32];

    int b    = blockIdx.x;
    int tid  = threadIdx.x;
    int lane = tid & 31;
    int row  = tid >> 5;

    int X0a = (b & 15) << 5;
    int Y0a = (b >> 4) << 5;
    int tb  = b + FIN_BLOCKS;
    int X0b = (tb & 15) << 5;
    int Y0b = (tb >> 4) << 5;

    int tBaseA = (Y0a + row) * MS + X0a + lane;
    int mRowA  = X0a + row;
    int mBaseA = mRowA * MS + (Y0a + lane);
    int iIdxA  = mRowA * NBY + (Y0a + lane);

    int tBaseB = (Y0b + row) * MS + X0b + lane;
    int mRowB  = X0b + row;
    int mBaseB = mRowB * MS + (Y0b + lane);
    int iIdxB  = mRowB * NBY + (Y0b + lane);

#if __CUDA_ARCH__ >= 900
    cudaGridDependencySynchronize();   // scatter completion => all REDs visible
#endif

    float a_t0 = g_T[0][tBaseA + 4];
    float a_t1 = g_T[1][tBaseA + 3];
    float a_t2 = g_T[2][tBaseA + 2];
    float a_t3 = g_T[3][tBaseA + 1];
    float b_t0 = g_T[0][tBaseB + 4];
    float b_t1 = g_T[1][tBaseB + 3];
    float b_t2 = g_T[2][tBaseB + 2];
    float b_t3 = g_T[3][tBaseB + 1];
    float a_m0 = g_M[0][mBaseA + 4];
    float a_m1 = g_M[1][mBaseA + 3];
    float a_m2 = g_M[2][mBaseA + 2];
    float a_m3 = g_M[3][mBaseA + 1];
    float b_m0 = g_M[0][mBaseB + 4];
    float b_m1 = g_M[1][mBaseB + 3];
    float b_m2 = g_M[2][mBaseB + 2];
    float b_m3 = g_M[3][mBaseB + 1];
    float a_i0 = initial[iIdxA];
    float b_i0 = initial[iIdxB];

    ts[0][row][lane] = a_t0 + a_t1 + a_t2 + a_t3;
    ts[1][row][lane] = b_t0 + b_t1 + b_t2 + b_t3;
    __syncthreads();

    float va = a_i0 + a_m0 + a_m1 + a_m2 + a_m3 + ts[0][lane][row];
    float vb = b_i0 + b_m0 + b_m1 + b_m2 + b_m3 + ts[1][lane][row];
    float da = va - TARGET_AREA;
    float db = vb - TARGET_AREA;
    float acc = da * da + db * db;

#pragma unroll
    for (int k = 0; k < 4; k++) {
        g_T[k][tBaseA + 4 - k] = 0.0f;
        g_T[k][tBaseB + 4 - k] = 0.0f;
    }
#pragma unroll
    for (int k = 0; k < 4; k++) {
        g_M[k][mBaseA + 4 - k] = 0.0f;
        g_M[k][mBaseB + 4 - k] = 0.0f;
    }

#pragma unroll
    for (int off = 16; off > 0; off >>= 1)
        acc += __shfl_xor_sync(0xFFFFFFFF, acc, off);
    if (lane == 0) sd[row] = acc;
    __syncthreads();
    if (tid < 32) {
        float v2 = sd[tid];
#pragma unroll
        for (int off = 16; off > 0; off >>= 1)
            v2 += __shfl_xor_sync(0xFFFFFFFF, v2, off);
        if (tid == 0) {
            atomicAdd(&g_sum, v2);
            __threadfence();
            int t = atomicAdd(&g_done, 1);
            if (t == (int)gridDim.x - 1) {
                out[0] = g_sum;
                g_sum  = 0.0f;         // restore invariants for next replay
                g_done = 0;
            }
        }
    }
}

// ---------------------------------------------------------------------------
extern "C" void kernel_launch(void* const* d_in, const int* in_sizes, int n_in,
                              void* d_out, int out_size) {
    const float* pos = (const float*)d_in[0];
    const float* sx  = (const float*)d_in[1];
    const float* sy  = (const float*)d_in[2];
    // d_in[3..8]: ax..cy — recomputed analytically; d_in[9..10]: bin centers — analytic
    const float* initial = (const float*)d_in[11];
    float* out = (float*)d_out;

    int n = in_sizes[1];

    scatter_kernel<<<(n + 255) / 256, 256>>>(pos, sx, sy, n);

    {
        cudaLaunchConfig_t cfg = {};
        cfg.gridDim  = dim3(FIN_BLOCKS, 1, 1);
        cfg.blockDim = dim3(1024, 1, 1);
        cfg.dynamicSmemBytes = 0;
        cfg.stream = 0;
        cudaLaunchAttribute attr[1];
        attr[0].id = cudaLaunchAttributeProgrammaticStreamSerialization;
        attr[0].val.programmaticStreamSerializationAllowed = 1;
        cfg.attrs = attr;
        cfg.numAttrs = 1;
        cudaLaunchKernelEx(&cfg, finish_kernel, initial, out);
    }
}